// round 4
// baseline (speedup 1.0000x reference)
#include <cuda_runtime.h>
#include <cuda_bf16.h>
#include <cstdint>

#define NN 25000
#define EE 400000
#define DD 256
#define FEAT 32
#define HOPS 4
#define SCAN_T 1024

// ---------------- device scratch (static, no allocation) ----------------
__device__ __align__(16) float g_h  [(size_t)NN * DD];
__device__ __align__(16) float g_h2 [(size_t)NN * DD];
__device__ __align__(16) float g_S  [(size_t)NN * DD];
__device__ __align__(16) float g_agg[(size_t)NN * DD];
__device__ __align__(16) float g_deg[NN];
__device__ __align__(16) float g_pool[DD];
__device__ int   g_cnt[NN];
__device__ int   g_rowptr[NN + 1];
__device__ int   g_pos[NN];
__device__ int   g_esrc[EE];
__device__ int   g_is64;

// read index idx from a buffer that is either int32 or int64
__device__ __forceinline__ int idx_at(const void* buf, int is64, size_t idx) {
    if (is64) return (int)((const long long*)buf)[idx];
    return ((const int*)buf)[idx];
}

// ---------------- dtype sniffer ----------------
// If edges is int64 (values in [0, 25000)), every odd 32-bit word is 0.
// If edges is int32, odd words are edge endpoint ids (not all zero).
__global__ void detect_kernel(const int* __restrict__ edges_w, int* __restrict__ is64) {
    __shared__ int nz;
    if (threadIdx.x == 0) nz = 0;
    __syncthreads();
    int any = 0;
    // sample odd words 1,3,...,8191
    for (int t = threadIdx.x; t < 4096; t += blockDim.x)
        if (edges_w[2 * t + 1] != 0) any = 1;
    if (any) atomicAdd(&nz, 1);
    __syncthreads();
    if (threadIdx.x == 0) *is64 = (nz == 0) ? 1 : 0;
}

// ---------------- utility ----------------
__global__ void zero_i_kernel(int* __restrict__ p, int n) {
    int i = blockIdx.x * blockDim.x + threadIdx.x;
    if (i < n) p[i] = 0;
}
__global__ void zero_f_kernel(float* __restrict__ p, int n) {
    int i = blockIdx.x * blockDim.x + threadIdx.x;
    if (i < n) p[i] = 0.0f;
}

// ---------------- CSR build ----------------
__global__ void count_kernel(const void* __restrict__ edges, const int* __restrict__ is64p,
                             int* __restrict__ cnt) {
    int e = blockIdx.x * blockDim.x + threadIdx.x;
    if (e >= EE) return;
    int d = idx_at(edges, *is64p, (size_t)EE + e);   // dst = row 1
    if (d >= 0 && d < NN) atomicAdd(&cnt[d], 1);
}

// single-block scan over NN counts -> rowptr[NN+1], pos, float degree
__global__ void scan_kernel(const int* __restrict__ cnt, int* __restrict__ rowptr,
                            int* __restrict__ pos, float* __restrict__ deg) {
    __shared__ int part[SCAN_T];
    int t = threadIdx.x;
    const int CH = (NN + SCAN_T - 1) / SCAN_T;  // 25
    int base = t * CH;
    int s = 0;
#pragma unroll
    for (int i = 0; i < CH; ++i) {
        int idx = base + i;
        if (idx < NN) s += cnt[idx];
    }
    part[t] = s;
    __syncthreads();
    for (int off = 1; off < SCAN_T; off <<= 1) {
        int v = (t >= off) ? part[t - off] : 0;
        __syncthreads();
        part[t] += v;
        __syncthreads();
    }
    int prefix = (t == 0) ? 0 : part[t - 1];
#pragma unroll
    for (int i = 0; i < CH; ++i) {
        int idx = base + i;
        if (idx < NN) {
            rowptr[idx] = prefix;
            pos[idx] = prefix;
            int c = cnt[idx];
            deg[idx] = (float)c;
            prefix += c;
        }
    }
    if (t == SCAN_T - 1) rowptr[NN] = part[SCAN_T - 1];
}

__global__ void fill_kernel(const void* __restrict__ edges, const int* __restrict__ is64p,
                            int* __restrict__ pos, int* __restrict__ esrc) {
    int e = blockIdx.x * blockDim.x + threadIdx.x;
    if (e >= EE) return;
    int is64 = *is64p;
    int s = idx_at(edges, is64, (size_t)e);            // src = row 0
    int d = idx_at(edges, is64, (size_t)EE + e);       // dst = row 1
    if (d < 0 || d >= NN) return;
    if (s < 0) s = 0; if (s >= NN) s = NN - 1;
    int slot = atomicAdd(&pos[d], 1);
    if (slot >= 0 && slot < EE) esrc[slot] = s;
}

// ---------------- initial node states ----------------
// h[v] = nodes[v] @ W_proj + b_proj + type_emb[type[v]]
__global__ void init_kernel(const float* __restrict__ nodes,
                            const void* __restrict__ types, const int* __restrict__ is64p,
                            const float* __restrict__ type_emb,
                            const float* __restrict__ W_proj,
                            const float* __restrict__ b_proj,
                            float* __restrict__ h) {
    int v = blockIdx.x;
    int j = threadIdx.x;
    __shared__ float sn[FEAT];
    if (j < FEAT) sn[j] = nodes[(size_t)v * FEAT + j];
    __syncthreads();
    int t = idx_at(types, *is64p, (size_t)v);
    if (t < 0) t = 0; if (t > 9) t = 9;
    float acc = b_proj[j] + type_emb[(size_t)t * DD + j];
#pragma unroll
    for (int k = 0; k < FEAT; ++k)
        acc += sn[k] * W_proj[(size_t)k * DD + j];
    h[(size_t)v * DD + j] = acc;
}

// ---------------- per-dst gather: S[v] = sum over incoming edges of h[src] ----
__global__ __launch_bounds__(DD)
void agg_gather_kernel(const int* __restrict__ rowptr,
                       const int* __restrict__ esrc,
                       const float* __restrict__ h,
                       float* __restrict__ S) {
    int v = blockIdx.x;
    int j = threadIdx.x;
    int beg = rowptr[v];
    int end = rowptr[v + 1];
    float acc = 0.0f;
    int i = beg;
    for (; i + 4 <= end; i += 4) {
        int s0 = esrc[i + 0];
        int s1 = esrc[i + 1];
        int s2 = esrc[i + 2];
        int s3 = esrc[i + 3];
        float a0 = h[(size_t)s0 * DD + j];
        float a1 = h[(size_t)s1 * DD + j];
        float a2 = h[(size_t)s2 * DD + j];
        float a3 = h[(size_t)s3 * DD + j];
        acc += (a0 + a1) + (a2 + a3);
    }
    for (; i < end; ++i)
        acc += h[(size_t)esrc[i] * DD + j];
    S[(size_t)v * DD + j] = acc;
}

// ---------------- fused dual-operand GEMM ----------------
// out[r][c] = sum_k P[r][k]*W[k][c] + rowscale[r]*sum_k Q[r][k]*W[256+k][c]
//             + bias[c]*(bias_scaled ? rowscale[r] : 1),  optional relu
#define BM 128
#define BN 128
#define BKK 8

__global__ __launch_bounds__(256)
void gemm2_kernel(const float* __restrict__ P,
                  const float* __restrict__ Q,
                  const float* __restrict__ W,
                  const float* __restrict__ bias,
                  const float* __restrict__ rowscale,
                  int bias_scaled, int do_relu,
                  float* __restrict__ out, int nrows) {
    __shared__ float As[BKK][BM];
    __shared__ float Bs[BKK][BN];

    int tid = threadIdx.x;
    int rowBase = blockIdx.y * BM;
    int colBase = blockIdx.x * BN;
    int tx = tid & 15;
    int ty = tid >> 4;

    float acc[8][8];
#pragma unroll
    for (int i = 0; i < 8; ++i)
#pragma unroll
        for (int j = 0; j < 8; ++j) acc[i][j] = 0.0f;

    int la_row = tid >> 1;
    int la_k   = (tid & 1) * 4;
    int lb_k   = tid >> 5;
    int lb_col = (tid & 31) * 4;

#pragma unroll 1
    for (int phase = 0; phase < 2; ++phase) {
        const float* X  = phase ? Q : P;
        const float* Wp = W + (size_t)phase * DD * DD;
        bool scaled = (phase == 1) && (rowscale != nullptr);
#pragma unroll 1
        for (int k0 = 0; k0 < DD; k0 += BKK) {
            int gr = rowBase + la_row;
            float4 av = make_float4(0.f, 0.f, 0.f, 0.f);
            if (gr < nrows) {
                av = *reinterpret_cast<const float4*>(X + (size_t)gr * DD + k0 + la_k);
                if (scaled) {
                    float sc = rowscale[gr];
                    av.x *= sc; av.y *= sc; av.z *= sc; av.w *= sc;
                }
            }
            As[la_k + 0][la_row] = av.x;
            As[la_k + 1][la_row] = av.y;
            As[la_k + 2][la_row] = av.z;
            As[la_k + 3][la_row] = av.w;
            float4 bv = *reinterpret_cast<const float4*>(
                Wp + (size_t)(k0 + lb_k) * DD + colBase + lb_col);
            *reinterpret_cast<float4*>(&Bs[lb_k][lb_col]) = bv;
            __syncthreads();
#pragma unroll
            for (int k = 0; k < BKK; ++k) {
                float a[8], b[8];
                *reinterpret_cast<float4*>(&a[0]) = *reinterpret_cast<const float4*>(&As[k][ty * 4]);
                *reinterpret_cast<float4*>(&a[4]) = *reinterpret_cast<const float4*>(&As[k][64 + ty * 4]);
                *reinterpret_cast<float4*>(&b[0]) = *reinterpret_cast<const float4*>(&Bs[k][tx * 4]);
                *reinterpret_cast<float4*>(&b[4]) = *reinterpret_cast<const float4*>(&Bs[k][64 + tx * 4]);
#pragma unroll
                for (int i = 0; i < 8; ++i)
#pragma unroll
                    for (int j = 0; j < 8; ++j)
                        acc[i][j] += a[i] * b[j];
            }
            __syncthreads();
        }
    }

#pragma unroll
    for (int i = 0; i < 8; ++i) {
        int rloc = (i < 4) ? (ty * 4 + i) : (64 + ty * 4 + i - 4);
        int r = rowBase + rloc;
        if (r >= nrows) continue;
        float bscale = 1.0f;
        if (bias_scaled) bscale = rowscale[r];
#pragma unroll
        for (int j = 0; j < 8; ++j) {
            int c = colBase + ((j < 4) ? (tx * 4 + j) : (64 + tx * 4 + j - 4));
            float v = acc[i][j] + bias[c] * bscale;
            if (do_relu) v = fmaxf(v, 0.0f);
            out[(size_t)r * DD + c] = v;
        }
    }
}

// ---------------- max pool over nodes ----------------
// post-relu values >= 0, so int-reinterpret atomicMax is order-preserving
__global__ void pool_kernel(const float* __restrict__ h, float* __restrict__ pool) {
    int j = threadIdx.x;
    int r0 = blockIdx.x * 256;
    int r1 = min(r0 + 256, NN);
    float m = 0.0f;
    for (int r = r0; r < r1; ++r)
        m = fmaxf(m, h[(size_t)r * DD + j]);
    atomicMax(reinterpret_cast<int*>(&pool[j]), __float_as_int(m));
}

// ---------------- final projection ----------------
__global__ void out_kernel(const float* __restrict__ pool,
                           const float* __restrict__ W_out,
                           const float* __restrict__ b_out,
                           float* __restrict__ out) {
    __shared__ float sp[DD];
    int j = threadIdx.x;
    sp[j] = pool[j];
    __syncthreads();
    float acc = b_out[j];
#pragma unroll 8
    for (int k = 0; k < DD; ++k)
        acc += sp[k] * W_out[(size_t)k * DD + j];
    out[j] = acc;
}

// ---------------- launch ----------------
extern "C" void kernel_launch(void* const* d_in, const int* in_sizes, int n_in,
                              void* d_out, int out_size) {
    const float* nodes      = (const float*)d_in[0];
    const void*  edges      = d_in[1];                 // [2, E] int32 or int64
    const void*  node_types = d_in[2];                 // [N]    int32 or int64
    const float* type_emb   = (const float*)d_in[3];
    const float* W_proj     = (const float*)d_in[4];
    const float* b_proj     = (const float*)d_in[5];
    const float* W_msg      = (const float*)d_in[6];   // [4, 512, 256]
    const float* b_msg      = (const float*)d_in[7];   // [4, 256]
    const float* W_upd      = (const float*)d_in[8];   // [4, 512, 256]
    const float* b_upd      = (const float*)d_in[9];   // [4, 256]
    const float* W_out      = (const float*)d_in[10];
    const float* b_out      = (const float*)d_in[11];
    float* out = (float*)d_out;

    float *h_p, *h2_p, *S_p, *agg_p, *deg_p, *pool_p;
    int *cnt_p, *rowptr_p, *pos_p, *esrc_p, *is64_p;
    cudaGetSymbolAddress((void**)&h_p,      g_h);
    cudaGetSymbolAddress((void**)&h2_p,     g_h2);
    cudaGetSymbolAddress((void**)&S_p,      g_S);
    cudaGetSymbolAddress((void**)&agg_p,    g_agg);
    cudaGetSymbolAddress((void**)&deg_p,    g_deg);
    cudaGetSymbolAddress((void**)&pool_p,   g_pool);
    cudaGetSymbolAddress((void**)&cnt_p,    g_cnt);
    cudaGetSymbolAddress((void**)&rowptr_p, g_rowptr);
    cudaGetSymbolAddress((void**)&pos_p,    g_pos);
    cudaGetSymbolAddress((void**)&esrc_p,   g_esrc);
    cudaGetSymbolAddress((void**)&is64_p,   g_is64);

    // sniff index dtype (int32 vs int64)
    detect_kernel<<<1, 256>>>((const int*)edges, is64_p);

    // CSR build (also yields float degree)
    zero_i_kernel<<<(NN + 255) / 256, 256>>>(cnt_p, NN);
    count_kernel<<<(EE + 255) / 256, 256>>>(edges, is64_p, cnt_p);
    scan_kernel<<<1, SCAN_T>>>(cnt_p, rowptr_p, pos_p, deg_p);
    fill_kernel<<<(EE + 255) / 256, 256>>>(edges, is64_p, pos_p, esrc_p);

    // initial states
    init_kernel<<<NN, DD>>>(nodes, node_types, is64_p, type_emb, W_proj, b_proj, h_p);

    float* h_cur = h_p;
    float* h_nxt = h2_p;
    dim3 ggrid(DD / BN, (NN + BM - 1) / BM);

    for (int i = 0; i < HOPS; ++i) {
        // S[v] = sum_{e: dst=v} h[src_e]   (gather, no atomics)
        agg_gather_kernel<<<NN, DD>>>(rowptr_p, esrc_p, h_cur, S_p);
        // agg = S @ Wm_top + deg .* (h @ Wm_bot) + deg .* b_msg
        gemm2_kernel<<<ggrid, 256>>>(S_p, h_cur,
                                     W_msg + (size_t)i * 2 * DD * DD,
                                     b_msg + (size_t)i * DD,
                                     deg_p, /*bias_scaled=*/1, /*relu=*/0,
                                     agg_p, NN);
        // h_next = relu(h @ Wu_top + agg @ Wu_bot + b_upd)
        gemm2_kernel<<<ggrid, 256>>>(h_cur, agg_p,
                                     W_upd + (size_t)i * 2 * DD * DD,
                                     b_upd + (size_t)i * DD,
                                     nullptr, /*bias_scaled=*/0, /*relu=*/1,
                                     h_nxt, NN);
        float* t = h_cur; h_cur = h_nxt; h_nxt = t;
    }

    // pool + output
    zero_f_kernel<<<1, DD>>>(pool_p, DD);
    pool_kernel<<<(NN + 255) / 256, DD>>>(h_cur, pool_p);
    out_kernel<<<1, DD>>>(pool_p, W_out, b_out, out);
}